// round 5
// baseline (speedup 1.0000x reference)
#include <cuda_runtime.h>
#include <cuda_bf16.h>

// Problem constants (fixed by dataset):
//   walk:  int32 [B=1024, L=80]
//   neg:   int32 [B=1024, A=76, NEG=4]
//   embed: f32   [1000000, D=128]
//   out:   f32 scalar = (sum softplus(-pos) + sum softplus(neg)) / (B*A*8)
#define L_WALK   80
#define W_WIN    5
#define A_ANC    (L_WALK - W_WIN + 1)     // 76
#define NNEG     4
#define DIM      128
#define NVEC     (DIM / 4)                // 32 float4 per row
#define NTHREADS 256
#define NWARPS   (NTHREADS / 32)

#define SPLIT    2
#define ANC_PER  (A_ANC / SPLIT)          // 38 anchors per block
#define ROWS_PER (ANC_PER + W_WIN - 1)    // 42 walk rows staged per block

static __global__ void zero_kernel(float* out) {
    if (threadIdx.x == 0) out[0] = 0.0f;
}

__device__ __forceinline__ float warp_reduce_sum(float v) {
    v += __shfl_xor_sync(0xffffffffu, v, 16);
    v += __shfl_xor_sync(0xffffffffu, v, 8);
    v += __shfl_xor_sync(0xffffffffu, v, 4);
    v += __shfl_xor_sync(0xffffffffu, v, 2);
    v += __shfl_xor_sync(0xffffffffu, v, 1);
    return v;
}

// Pairwise combining reduce: lanes with (lane & off)==0 end up holding the
// a-reduction, lanes with the bit set hold the b-reduction.
__device__ __forceinline__ float cmb(float a, float b, int off, int lane) {
    float send = (lane & off) ? a : b;
    float keep = (lane & off) ? b : a;
    return keep + __shfl_xor_sync(0xffffffffu, send, off);
}

// softplus(x) = max(x,0) + log(1 + exp(-|x|)); fast-math variants are
// accurate to ~1e-7 absolute here, far inside the 1e-3 rel-err budget.
__device__ __forceinline__ float softplus_f(float x) {
    return fmaxf(x, 0.0f) + __logf(1.0f + __expf(-fabsf(x)));
}

__device__ __forceinline__ float dot4(float4 a, float4 b) {
    return a.x * b.x + a.y * b.y + a.z * b.z + a.w * b.w;
}

__global__ __launch_bounds__(NTHREADS, 6)
void sgns_kernel(const int* __restrict__ walk,
                 const int* __restrict__ neg,
                 const float* __restrict__ embed,
                 float* __restrict__ out,
                 float inv_total) {
    __shared__ float4 srow[ROWS_PER][NVEC];   // 42 x 512B = 21.5 KB
    __shared__ int    swalk[ROWS_PER];
    __shared__ int    sneg[ANC_PER * NNEG];   // 152 ints
    __shared__ float  wsum[NWARPS];

    const int bid  = blockIdx.x;
    const int wb   = bid >> 1;                // walk index
    const int base = (bid & 1) * ANC_PER;     // first anchor of this half
    const int tid  = threadIdx.x;
    const int lane = tid & 31;
    const int wid  = tid >> 5;

    if (tid < ROWS_PER)
        swalk[tid] = walk[(size_t)wb * L_WALK + base + tid];
    if (tid < ANC_PER * NNEG)
        sneg[tid] = neg[((size_t)wb * A_ANC + base) * NNEG + tid];
    __syncthreads();

    // Stage the 42 walk-row embeddings into shared memory (coalesced 512B rows).
    for (int r = wid; r < ROWS_PER; r += NWARPS) {
        const float4* src = (const float4*)(embed + (size_t)swalk[r] * DIM);
        srow[r][lane] = __ldg(src + lane);
    }
    __syncthreads();

    float acc = 0.0f;   // per-lane partial (8 softplus lanes contribute)

    // Software-pipelined gathers: v* holds the in-flight loads for the
    // current anchor; at iteration start we immediately issue the NEXT
    // anchor's 4 gathers into w* so ~8 loads/warp stay outstanding.
    float4 v0, v1, v2, v3;
    if (wid < ANC_PER) {
        const int i0 = sneg[wid * NNEG + 0];
        const int i1 = sneg[wid * NNEG + 1];
        const int i2 = sneg[wid * NNEG + 2];
        const int i3 = sneg[wid * NNEG + 3];
        v0 = __ldg((const float4*)(embed + (size_t)i0 * DIM) + lane);
        v1 = __ldg((const float4*)(embed + (size_t)i1 * DIM) + lane);
        v2 = __ldg((const float4*)(embed + (size_t)i2 * DIM) + lane);
        v3 = __ldg((const float4*)(embed + (size_t)i3 * DIM) + lane);
    }

    for (int a = wid; a < ANC_PER; a += NWARPS) {
        // Prefetch next anchor's gathers (warp-uniform guard, no divergence).
        const int an = a + NWARPS;
        float4 w0, w1, w2, w3;
        const bool have_next = (an < ANC_PER);
        if (have_next) {
            const int j0 = sneg[an * NNEG + 0];
            const int j1 = sneg[an * NNEG + 1];
            const int j2 = sneg[an * NNEG + 2];
            const int j3 = sneg[an * NNEG + 3];
            w0 = __ldg((const float4*)(embed + (size_t)j0 * DIM) + lane);
            w1 = __ldg((const float4*)(embed + (size_t)j1 * DIM) + lane);
            w2 = __ldg((const float4*)(embed + (size_t)j2 * DIM) + lane);
            w3 = __ldg((const float4*)(embed + (size_t)j3 * DIM) + lane);
        }

        const float4 va = srow[a][lane];

        // Positive contexts (smem, reused 5x per row).
        const float p0 = dot4(va, srow[a + 1][lane]);
        const float p1 = dot4(va, srow[a + 2][lane]);
        const float p2 = dot4(va, srow[a + 3][lane]);
        const float p3 = dot4(va, srow[a + 4][lane]);

        // Negative dots (consume the gathers issued LAST iteration).
        const float p4 = dot4(va, v0);
        const float p5 = dot4(va, v1);
        const float p6 = dot4(va, v2);
        const float p7 = dot4(va, v3);

        // Multi-value warp reduction: 9 shfls reduce all 8 dots.
        //   bit16 -> pos vs neg, bits {8,4} -> which of the 4 within group.
        float r10 = cmb(p0, p4, 16, lane);
        float r11 = cmb(p1, p5, 16, lane);
        float r12 = cmb(p2, p6, 16, lane);
        float r13 = cmb(p3, p7, 16, lane);
        float q0  = cmb(r10, r11, 8, lane);
        float q1  = cmb(r12, r13, 8, lane);
        float r   = cmb(q0, q1, 4, lane);
        r += __shfl_xor_sync(0xffffffffu, r, 2);
        r += __shfl_xor_sync(0xffffffffu, r, 1);

        // Lanes 0,4,8,...,28 each hold one of the 8 full dot products.
        // bit16 set => negative-sample logit (softplus(+x)), else softplus(-x).
        if ((lane & 3) == 0) {
            const float x = (lane & 16) ? r : -r;
            acc += softplus_f(x);
        }

        if (have_next) { v0 = w0; v1 = w1; v2 = w2; v3 = w3; }
    }

    acc = warp_reduce_sum(acc);
    if (lane == 0) wsum[wid] = acc;
    __syncthreads();

    if (tid == 0) {
        float s = 0.0f;
        #pragma unroll
        for (int i = 0; i < NWARPS; i++) s += wsum[i];
        atomicAdd(out, s * inv_total);
    }
}

extern "C" void kernel_launch(void* const* d_in, const int* in_sizes, int n_in,
                              void* d_out, int out_size) {
    const int*   walk  = (const int*)d_in[0];
    const int*   neg   = (const int*)d_in[1];
    const float* embed = (const float*)d_in[2];
    float*       out   = (float*)d_out;

    const int B = in_sizes[0] / L_WALK;                 // 1024
    const float inv_total = 1.0f / ((float)B * A_ANC * (W_WIN - 1 + NNEG));

    zero_kernel<<<1, 32>>>(out);
    sgns_kernel<<<B * SPLIT, NTHREADS>>>(walk, neg, embed, out, inv_total);
}

// round 6
// speedup vs baseline: 1.4740x; 1.4740x over previous
#include <cuda_runtime.h>
#include <cuda_bf16.h>

// Problem constants (fixed by dataset):
//   walk:  int32 [B=1024, L=80]
//   neg:   int32 [B=1024, A=76, NEG=4]
//   embed: f32   [1000000, D=128]
//   out:   f32 scalar = (sum softplus(-pos) + sum softplus(neg)) / (B*A*8)
#define L_WALK   80
#define W_WIN    5
#define A_ANC    (L_WALK - W_WIN + 1)     // 76
#define NNEG     4
#define DIM      128
#define NVEC     (DIM / 4)                // 32 float4 per row
#define NTHREADS 256
#define NWARPS   (NTHREADS / 32)

#define SPLIT    2
#define ANC_PER  (A_ANC / SPLIT)          // 38 anchors per block
#define ROWS_PER (ANC_PER + W_WIN - 1)    // 42 walk rows staged per block

static __global__ void zero_kernel(float* out) {
    if (threadIdx.x == 0) out[0] = 0.0f;
}

__device__ __forceinline__ float warp_reduce_sum(float v) {
    v += __shfl_xor_sync(0xffffffffu, v, 16);
    v += __shfl_xor_sync(0xffffffffu, v, 8);
    v += __shfl_xor_sync(0xffffffffu, v, 4);
    v += __shfl_xor_sync(0xffffffffu, v, 2);
    v += __shfl_xor_sync(0xffffffffu, v, 1);
    return v;
}

// Pairwise combining reduce: lanes with (lane & off)==0 end up holding the
// a-reduction, lanes with the bit set hold the b-reduction.
__device__ __forceinline__ float cmb(float a, float b, int off, int lane) {
    float send = (lane & off) ? a : b;
    float keep = (lane & off) ? b : a;
    return keep + __shfl_xor_sync(0xffffffffu, send, off);
}

// softplus(x) = max(x,0) + log(1 + exp(-|x|)); fast-math variants are
// accurate to ~1e-7 absolute here, far inside the 1e-3 rel-err budget.
__device__ __forceinline__ float softplus_f(float x) {
    return fmaxf(x, 0.0f) + __logf(1.0f + __expf(-fabsf(x)));
}

__device__ __forceinline__ float dot4(float4 a, float4 b) {
    return a.x * b.x + a.y * b.y + a.z * b.z + a.w * b.w;
}

__global__ __launch_bounds__(NTHREADS, 6)
void sgns_kernel(const int* __restrict__ walk,
                 const int* __restrict__ neg,
                 const float* __restrict__ embed,
                 float* __restrict__ out,
                 float inv_total) {
    __shared__ float4 srow[ROWS_PER][NVEC];   // 42 x 512B = 21.5 KB
    __shared__ int    swalk[ROWS_PER];
    __shared__ int    sneg[ANC_PER * NNEG];   // 152 ints
    __shared__ float  wsum[NWARPS];

    const int bid  = blockIdx.x;
    const int wb   = bid >> 1;                // walk index
    const int base = (bid & 1) * ANC_PER;     // first anchor of this half
    const int tid  = threadIdx.x;
    const int lane = tid & 31;
    const int wid  = tid >> 5;

    if (tid < ROWS_PER)
        swalk[tid] = walk[(size_t)wb * L_WALK + base + tid];
    if (tid < ANC_PER * NNEG)
        sneg[tid] = neg[((size_t)wb * A_ANC + base) * NNEG + tid];
    __syncthreads();

    // Stage the 42 walk-row embeddings into shared memory (coalesced 512B rows).
    for (int r = wid; r < ROWS_PER; r += NWARPS) {
        const float4* src = (const float4*)(embed + (size_t)swalk[r] * DIM);
        srow[r][lane] = __ldg(src + lane);
    }
    __syncthreads();

    float acc = 0.0f;   // per-lane partial (8 softplus lanes contribute)

    // Pipelined gathers with IN-PLACE register reuse: v0..v3 always hold the
    // gathers for the CURRENT anchor; as soon as each pair is consumed, the
    // same registers are refilled with the NEXT anchor's rows. All 4 next
    // loads are in flight during the reduction/softplus tail, at the same
    // register cost as the unpipelined version (16 buffer regs).
    float4 v0, v1, v2, v3;
    {
        const int a0 = wid;   // NWARPS(8) <= ANC_PER(38), always valid
        v0 = __ldg((const float4*)(embed + (size_t)sneg[a0 * NNEG + 0] * DIM) + lane);
        v1 = __ldg((const float4*)(embed + (size_t)sneg[a0 * NNEG + 1] * DIM) + lane);
        v2 = __ldg((const float4*)(embed + (size_t)sneg[a0 * NNEG + 2] * DIM) + lane);
        v3 = __ldg((const float4*)(embed + (size_t)sneg[a0 * NNEG + 3] * DIM) + lane);
    }

    for (int a = wid; a < ANC_PER; a += NWARPS) {
        const float4 va = srow[a][lane];

        // Positive contexts (smem, reused 5x per row).
        const float p0 = dot4(va, srow[a + 1][lane]);
        const float p1 = dot4(va, srow[a + 2][lane]);
        const float p2 = dot4(va, srow[a + 3][lane]);
        const float p3 = dot4(va, srow[a + 4][lane]);

        const int  an = a + NWARPS;
        const bool hn = (an < ANC_PER);     // warp-uniform

        // Consume v0,v1 then refill them in place with next anchor's rows.
        const float p4 = dot4(va, v0);
        const float p5 = dot4(va, v1);
        if (hn) {
            v0 = __ldg((const float4*)(embed + (size_t)sneg[an * NNEG + 0] * DIM) + lane);
            v1 = __ldg((const float4*)(embed + (size_t)sneg[an * NNEG + 1] * DIM) + lane);
        }
        const float p6 = dot4(va, v2);
        const float p7 = dot4(va, v3);
        if (hn) {
            v2 = __ldg((const float4*)(embed + (size_t)sneg[an * NNEG + 2] * DIM) + lane);
            v3 = __ldg((const float4*)(embed + (size_t)sneg[an * NNEG + 3] * DIM) + lane);
        }

        // Multi-value warp reduction: 9 shfls reduce all 8 dots.
        //   bit16 -> pos vs neg, bits {8,4} -> which of the 4 within group.
        // The 4 prefetch LDGs above stay in flight through this whole tail.
        float r10 = cmb(p0, p4, 16, lane);
        float r11 = cmb(p1, p5, 16, lane);
        float r12 = cmb(p2, p6, 16, lane);
        float r13 = cmb(p3, p7, 16, lane);
        float q0  = cmb(r10, r11, 8, lane);
        float q1  = cmb(r12, r13, 8, lane);
        float r   = cmb(q0, q1, 4, lane);
        r += __shfl_xor_sync(0xffffffffu, r, 2);
        r += __shfl_xor_sync(0xffffffffu, r, 1);

        // Lanes 0,4,8,...,28 each hold one of the 8 full dot products.
        // bit16 set => negative-sample logit (softplus(+x)), else softplus(-x).
        if ((lane & 3) == 0) {
            const float x = (lane & 16) ? r : -r;
            acc += softplus_f(x);
        }
    }

    acc = warp_reduce_sum(acc);
    if (lane == 0) wsum[wid] = acc;
    __syncthreads();

    if (tid == 0) {
        float s = 0.0f;
        #pragma unroll
        for (int i = 0; i < NWARPS; i++) s += wsum[i];
        atomicAdd(out, s * inv_total);
    }
}

extern "C" void kernel_launch(void* const* d_in, const int* in_sizes, int n_in,
                              void* d_out, int out_size) {
    const int*   walk  = (const int*)d_in[0];
    const int*   neg   = (const int*)d_in[1];
    const float* embed = (const float*)d_in[2];
    float*       out   = (float*)d_out;

    const int B = in_sizes[0] / L_WALK;                 // 1024
    const float inv_total = 1.0f / ((float)B * A_ANC * (W_WIN - 1 + NNEG));

    zero_kernel<<<1, 32>>>(out);
    sgns_kernel<<<B * SPLIT, NTHREADS>>>(walk, neg, embed, out, inv_total);
}